// round 13
// baseline (speedup 1.0000x reference)
#include <cuda_runtime.h>
#include <cuda_fp16.h>
#include <cuda_fp8.h>
#include <cstdint>
#include <math.h>

#define NB 4
#define NN 4096
#define NM 4096
#define ND 256
#define ND0 128
#define NK 64
#define GITERS 8            // 4 fp8 cross iters + 4 fp16 hi*hi iters (128B of K each)
#define THRESH 0.01f
#define EPS_G 1e-6f
#define LO_SCALE 131072.0f  // 2^17
#define HI_SCALE 16.0f      // 2^4
#define CROSS_INV (1.0f / (131072.0f * 16.0f))  // 2^-21
#define GSMEM (3 * 32768)   // 3 stages x (A 16KB + B 16KB)

// ---------------- scratch ----------------
static __device__ __align__(16) __half g_Ah[(size_t)NB * NN * 256];
static __device__ __align__(16) __half g_Bh[(size_t)NB * NM * 256];
static __device__ __align__(16) unsigned char g_Ax[(size_t)NB * NN * 512];
static __device__ __align__(16) unsigned char g_Bx[(size_t)NB * NM * 512];
static __device__ float g_sim[(size_t)NB * NN * NM];   // holds e = exp(sim)
static __device__ float g_rowinv[NB * NN];
static __device__ float g_colinv[NB * NM];
static __device__ float g_rowsum_part[NB * NN * 32];
static __device__ float g_colsum_part[NB * NM * 32];
static __device__ int g_rowj[NB * NN];
static __device__ float g_rowP[NB * NN];
static __device__ unsigned g_colmaxP[NB * NM];

__device__ __forceinline__ uint32_t smem_to_u32(const void* p) {
    uint32_t a;
    asm("{ .reg .u64 t; cvta.to.shared.u64 t, %1; cvt.u32.u64 %0, t; }" : "=r"(a) : "l"(p));
    return a;
}

// CUTLASS-style crosswise swizzle for 64B rows: 16B group XOR (row & 3)
__device__ __forceinline__ uint32_t swz(uint32_t r, uint32_t bytecol) {
    return r * 64 + ((((bytecol >> 4) & 3) ^ (r & 3)) << 4) + (bytecol & 15);
}

__device__ __forceinline__ void cpasync16(uint32_t dst, const void* src) {
    asm volatile("cp.async.cg.shared.global [%0], [%1], 16;" :: "r"(dst), "l"(src));
}

__device__ __forceinline__ void ldsm4(uint32_t& d0, uint32_t& d1, uint32_t& d2, uint32_t& d3,
                                      uint32_t addr) {
    asm volatile("ldmatrix.sync.aligned.m8n8.x4.shared.b16 {%0,%1,%2,%3}, [%4];"
                 : "=r"(d0), "=r"(d1), "=r"(d2), "=r"(d3) : "r"(addr));
}

__device__ __forceinline__ void mma16816(float* c, const uint32_t* a, const uint32_t* b) {
    asm volatile(
        "mma.sync.aligned.m16n8k16.row.col.f32.f16.f16.f32 "
        "{%0,%1,%2,%3}, {%4,%5,%6,%7}, {%8,%9}, {%0,%1,%2,%3};"
        : "+f"(c[0]), "+f"(c[1]), "+f"(c[2]), "+f"(c[3])
        : "r"(a[0]), "r"(a[1]), "r"(a[2]), "r"(a[3]), "r"(b[0]), "r"(b[1]));
}

__device__ __forceinline__ void mma16832q(float* c, const uint32_t* a, const uint32_t* b) {
    asm volatile(
        "mma.sync.aligned.m16n8k32.row.col.f32.e4m3.e4m3.f32 "
        "{%0,%1,%2,%3}, {%4,%5,%6,%7}, {%8,%9}, {%0,%1,%2,%3};"
        : "+f"(c[0]), "+f"(c[1]), "+f"(c[2]), "+f"(c[3])
        : "r"(a[0]), "r"(a[1]), "r"(a[2]), "r"(a[3]), "r"(b[0]), "r"(b[1]));
}

// ---------------- normalize + split (covers 2 batches of A + B rows) ----------------
__global__ void normalize_split_kernel(const float* __restrict__ descA,
                                       const float* __restrict__ descB,
                                       int rowbase) {
    int blk = blockIdx.x;  // 0..16383
    bool isA = blk < 2 * NN;
    int r = rowbase + (isA ? blk : blk - 2 * NN);
    if (isA && threadIdx.x == 0) g_colmaxP[r] = 0u;
    const float* src = (isA ? descA : descB) + (size_t)r * ND;
    int t = threadIdx.x;  // 256
    float v = src[t];
    float s = v * v;
#pragma unroll
    for (int o = 16; o; o >>= 1) s += __shfl_xor_sync(0xffffffffu, s, o);
    __shared__ float ws[8];
    if ((t & 31) == 0) ws[t >> 5] = s;
    __syncthreads();
    float tot = ws[0] + ws[1] + ws[2] + ws[3] + ws[4] + ws[5] + ws[6] + ws[7];
    float nv = v / sqrtf(tot);
    __half hi = __float2half_rn(nv);
    float lof = (nv - __half2float(hi)) * LO_SCALE;
    float hif = nv * HI_SCALE;
    unsigned char loq = (unsigned char)__nv_cvt_float_to_fp8(lof, __NV_SATFINITE, __NV_E4M3);
    unsigned char hiq = (unsigned char)__nv_cvt_float_to_fp8(hif, __NV_SATFINITE, __NV_E4M3);
    if (isA) {
        g_Ah[(size_t)r * 256 + t] = hi;
        g_Ax[(size_t)r * 512 + t] = loq;        // A cross = [lo' | hi']
        g_Ax[(size_t)r * 512 + 256 + t] = hiq;
    } else {
        g_Bh[(size_t)r * 256 + t] = hi;
        g_Bx[(size_t)r * 512 + t] = hiq;        // B cross = [hi' | lo']
        g_Bx[(size_t)r * 512 + 256 + t] = loq;
    }
}

// ---------------- GEMM (R10 config): 128x128 tile, 8 warps, 3-stage x 32KB ----------------
__global__ __launch_bounds__(256, 2) void gemm16_kernel(int bbase) {
    extern __shared__ __align__(128) char buf[];

    int tid = threadIdx.x, lane = tid & 31, wid = tid >> 5;
    int warp_m = wid & 1;
    int warp_n = wid >> 1;
    int b = bbase + blockIdx.z;
    int m0 = blockIdx.x * 128;
    int n0 = blockIdx.y * 128;
    uint32_t sbase = smem_to_u32(buf);

    int lr = tid >> 1;
    int ls = (tid & 1) * 2;

    const char* Agx = (const char*)g_Ax + ((size_t)b * NN + n0 + lr) * 512 + ls * 16;
    const char* Bgx = (const char*)g_Bx + ((size_t)b * NM + m0 + lr) * 512 + ls * 16;
    const char* Agh = (const char*)g_Ah + ((size_t)b * NN + n0 + lr) * 512 + ls * 16;
    const char* Bgh = (const char*)g_Bh + ((size_t)b * NM + m0 + lr) * 512 + ls * 16;

    uint32_t pf0 = swz((uint32_t)lr, (uint32_t)ls * 16);
    uint32_t pf1 = swz((uint32_t)lr, (uint32_t)(ls + 1) * 16);

    uint32_t offA[2][4], offB[2][2];
#pragma unroll
    for (int ks = 0; ks < 2; ++ks) {
#pragma unroll
        for (int mf = 0; mf < 4; ++mf)
            offA[ks][mf] = swz(warp_m * 64 + mf * 16 + (lane & 15),
                               ks * 32 + (lane >> 4) * 16);
#pragma unroll
        for (int np = 0; np < 2; ++np)
            offB[ks][np] = swz(warp_n * 32 + np * 16 + (lane & 7) + ((lane >> 4) << 3),
                               ks * 32 + ((lane >> 3) & 1) * 16);
    }

    auto prefetch = [&](int it2) {
        int slot = it2 % 3;
        const char *Ab_, *Bb_;
        if (it2 < 4) { Ab_ = Agx + it2 * 128; Bb_ = Bgx + it2 * 128; }
        else         { Ab_ = Agh + (it2 - 4) * 128; Bb_ = Bgh + (it2 - 4) * 128; }
        uint32_t as_ = sbase + slot * 32768;
        uint32_t bs_ = as_ + 16384;
        cpasync16(as_ + pf0, Ab_);
        cpasync16(as_ + pf1, Ab_ + 16);
        cpasync16(as_ + 8192 + pf0, Ab_ + 64);
        cpasync16(as_ + 8192 + pf1, Ab_ + 80);
        cpasync16(bs_ + pf0, Bb_);
        cpasync16(bs_ + pf1, Bb_ + 16);
        cpasync16(bs_ + 8192 + pf0, Bb_ + 64);
        cpasync16(bs_ + 8192 + pf1, Bb_ + 80);
        asm volatile("cp.async.commit_group;" ::: "memory");
    };

    prefetch(0);
    prefetch(1);

    float acc[4][4][4];
#pragma unroll
    for (int i = 0; i < 4; i++)
#pragma unroll
        for (int j = 0; j < 4; j++)
#pragma unroll
            for (int k = 0; k < 4; k++) acc[i][j][k] = 0.f;

    // ---- phase 1: cross terms, fp8 e4m3 ----
#pragma unroll 1
    for (int it = 0; it < 4; ++it) {
        if (it < GITERS - 2) {
            asm volatile("cp.async.wait_group 1;" ::: "memory");
        } else {
            asm volatile("cp.async.wait_group 0;" ::: "memory");
        }
        __syncthreads();
        if (it + 2 < GITERS) prefetch(it + 2);

        int slot = it % 3;
        uint32_t ab0 = sbase + slot * 32768;
        uint32_t bb0 = ab0 + 16384;
#pragma unroll
        for (int ks = 0; ks < 4; ++ks) {
            uint32_t ab = ab0 + (ks >> 1) * 8192, bb = bb0 + (ks >> 1) * 8192;
            int kl = ks & 1;
            uint32_t a[4][4];
#pragma unroll
            for (int mf = 0; mf < 4; ++mf)
                ldsm4(a[mf][0], a[mf][1], a[mf][2], a[mf][3], ab + offA[kl][mf]);
            uint32_t bf[4][2];
#pragma unroll
            for (int np = 0; np < 2; ++np) {
                uint32_t r0, r1, r2, r3;
                ldsm4(r0, r1, r2, r3, bb + offB[kl][np]);
                bf[np * 2][0] = r0; bf[np * 2][1] = r1;
                bf[np * 2 + 1][0] = r2; bf[np * 2 + 1][1] = r3;
            }
#pragma unroll
            for (int mf = 0; mf < 4; ++mf)
#pragma unroll
                for (int nf = 0; nf < 4; ++nf) mma16832q(acc[mf][nf], a[mf], bf[nf]);
        }
    }

    // ---- scale cross contribution ----
#pragma unroll
    for (int mf = 0; mf < 4; ++mf)
#pragma unroll
        for (int nf = 0; nf < 4; ++nf)
#pragma unroll
            for (int k = 0; k < 4; ++k) acc[mf][nf][k] *= CROSS_INV;

    // ---- phase 2: hi*hi, fp16 fp32-acc ----
#pragma unroll 1
    for (int it = 4; it < 8; ++it) {
        if (it < GITERS - 2) {
            asm volatile("cp.async.wait_group 1;" ::: "memory");
        } else {
            asm volatile("cp.async.wait_group 0;" ::: "memory");
        }
        __syncthreads();
        if (it + 2 < GITERS) prefetch(it + 2);

        int slot = it % 3;
        uint32_t ab0 = sbase + slot * 32768;
        uint32_t bb0 = ab0 + 16384;
#pragma unroll
        for (int ks = 0; ks < 4; ++ks) {
            uint32_t ab = ab0 + (ks >> 1) * 8192, bb = bb0 + (ks >> 1) * 8192;
            int kl = ks & 1;
            uint32_t a[4][4];
#pragma unroll
            for (int mf = 0; mf < 4; ++mf)
                ldsm4(a[mf][0], a[mf][1], a[mf][2], a[mf][3], ab + offA[kl][mf]);
            uint32_t bf[4][2];
#pragma unroll
            for (int np = 0; np < 2; ++np) {
                uint32_t r0, r1, r2, r3;
                ldsm4(r0, r1, r2, r3, bb + offB[kl][np]);
                bf[np * 2][0] = r0; bf[np * 2][1] = r1;
                bf[np * 2 + 1][0] = r2; bf[np * 2 + 1][1] = r3;
            }
#pragma unroll
            for (int mf = 0; mf < 4; ++mf)
#pragma unroll
                for (int nf = 0; nf < 4; ++nf) mma16816(acc[mf][nf], a[mf], bf[nf]);
        }
    }
    __syncthreads();  // compute done; reuse buf as reduction scratch

    float (*rowred)[4] = (float(*)[4])buf;
    float (*colred)[2] = (float(*)[2])(buf + 2048);

    // ---------- epilogue: e = __expf(20*acc), streaming store, partial sums ----------
    int qt = lane >> 2;
    int qc = lane & 3;
    float rsl[4][2];
    float csl[4][2];
#pragma unroll
    for (int i = 0; i < 4; i++) { rsl[i][0] = rsl[i][1] = 0.f; csl[i][0] = csl[i][1] = 0.f; }

    float* S = g_sim + (size_t)b * NN * NM;
#pragma unroll
    for (int mf = 0; mf < 4; ++mf) {
#pragma unroll
        for (int h = 0; h < 2; ++h) {
            int gr = n0 + warp_m * 64 + mf * 16 + qt + 8 * h;
            float* Sr = S + (size_t)gr * NM + m0 + warp_n * 32;
#pragma unroll
            for (int nf = 0; nf < 4; ++nf) {
                float e0 = __expf(20.0f * acc[mf][nf][h * 2 + 0]);
                float e1 = __expf(20.0f * acc[mf][nf][h * 2 + 1]);
                __stcs((float2*)(Sr + nf * 8 + qc * 2), make_float2(e0, e1));
                rsl[mf][h] += e0 + e1;
                csl[nf][0] += e0;
                csl[nf][1] += e1;
            }
        }
    }

#pragma unroll
    for (int mf = 0; mf < 4; ++mf)
#pragma unroll
        for (int h = 0; h < 2; ++h) {
            float v = rsl[mf][h];
            v += __shfl_xor_sync(0xffffffffu, v, 1);
            v += __shfl_xor_sync(0xffffffffu, v, 2);
            if (qc == 0) rowred[warp_m * 64 + mf * 16 + qt + 8 * h][warp_n] = v;
        }
#pragma unroll
    for (int nf = 0; nf < 4; ++nf)
#pragma unroll
        for (int c = 0; c < 2; ++c) {
            float v = csl[nf][c];
            v += __shfl_xor_sync(0xffffffffu, v, 4);
            v += __shfl_xor_sync(0xffffffffu, v, 8);
            v += __shfl_xor_sync(0xffffffffu, v, 16);
            if (qt == 0) colred[warp_n * 32 + nf * 8 + qc * 2 + c][warp_m] = v;
        }
    __syncthreads();

    if (tid < 128) {
        float rv = rowred[tid][0] + rowred[tid][1] + rowred[tid][2] + rowred[tid][3];
        g_rowsum_part[((size_t)b * NN + n0 + tid) * 32 + blockIdx.x] = rv;
        float cv = colred[tid][0] + colred[tid][1];
        g_colsum_part[((size_t)b * NM + m0 + tid) * 32 + blockIdx.y] = cv;
    }
}

// ---------------- per-batch sum reduction -> reciprocals ----------------
__global__ void reduce_sums_kernel(int b) {
    int warp = (blockIdx.x * blockDim.x + threadIdx.x) >> 5;  // 0..8191
    int lane = threadIdx.x & 31;
    if (warp < NN) {
        int i = b * NN + warp;
        float v = g_rowsum_part[(size_t)i * 32 + lane];
#pragma unroll
        for (int o = 16; o; o >>= 1) v += __shfl_xor_sync(0xffffffffu, v, o);
        if (lane == 0) g_rowinv[i] = 1.0f / v;
    } else {
        int k = b * NM + (warp - NN);
        float v = g_colsum_part[(size_t)k * 32 + lane];
#pragma unroll
        for (int o = 16; o; o >>= 1) v += __shfl_xor_sync(0xffffffffu, v, o);
        if (lane == 0) g_colinv[k] = 1.0f / v;
    }
}

// ---------------- P pass: warp-per-4-rows, shared colmax ----------------
__global__ __launch_bounds__(256) void pmat_kernel(int b) {
    __shared__ unsigned scm[NM];  // 16 KB column max of p
    int tid = threadIdx.x, lane = tid & 31, w = tid >> 5;
    int row0 = blockIdx.x * 32 + w * 4;
    const float* S = g_sim + (size_t)b * NN * NM + (size_t)row0 * NM;
    const float* CI = g_colinv + b * NM;

    for (int i = tid; i < NM; i += 256) scm[i] = 0u;

    float ri[4];
#pragma unroll
    for (int r = 0; r < 4; ++r) ri[r] = __ldg(&g_rowinv[b * NN + row0 + r]);

    __syncthreads();

    float best[4] = {-1.f, -1.f, -1.f, -1.f};
    int bm[4] = {0, 0, 0, 0};

#pragma unroll 1
    for (int k = 0; k < 32; ++k) {
        int c = k * 128 + lane * 4;
        float4 civ = __ldg((const float4*)(CI + c));
        float cm[4] = {0.f, 0.f, 0.f, 0.f};
#pragma unroll
        for (int r = 0; r < 4; ++r) {
            float4 e = __ldcs((const float4*)(S + (size_t)r * NM + c));
            float q0 = (e.x * e.x) * civ.x;
            float q1 = (e.y * e.y) * civ.y;
            float q2 = (e.z * e.z) * civ.z;
            float q3 = (e.w * e.w) * civ.w;
            if (q0 > best[r]) { best[r] = q0; bm[r] = c; }
            if (q1 > best[r]) { best[r] = q1; bm[r] = c + 1; }
            if (q2 > best[r]) { best[r] = q2; bm[r] = c + 2; }
            if (q3 > best[r]) { best[r] = q3; bm[r] = c + 3; }
            cm[0] = fmaxf(cm[0], q0 * ri[r]);
            cm[1] = fmaxf(cm[1], q1 * ri[r]);
            cm[2] = fmaxf(cm[2], q2 * ri[r]);
            cm[3] = fmaxf(cm[3], q3 * ri[r]);
        }
        atomicMax(&scm[c + 0], __float_as_uint(cm[0]));
        atomicMax(&scm[c + 1], __float_as_uint(cm[1]));
        atomicMax(&scm[c + 2], __float_as_uint(cm[2]));
        atomicMax(&scm[c + 3], __float_as_uint(cm[3]));
    }

#pragma unroll
    for (int r = 0; r < 4; ++r) {
        float bq = best[r];
        int bj = bm[r];
#pragma unroll
        for (int o = 16; o; o >>= 1) {
            float ob = __shfl_xor_sync(0xffffffffu, bq, o);
            int obj = __shfl_xor_sync(0xffffffffu, bj, o);
            if (ob > bq || (ob == bq && obj < bj)) { bq = ob; bj = obj; }
        }
        if (lane == 0) {
            g_rowj[b * NN + row0 + r] = bj;
            g_rowP[b * NN + row0 + r] = bq * ri[r];
        }
    }

    __syncthreads();
    for (int i = tid; i < NM; i += 256)
        atomicMax(&g_colmaxP[b * NM + i], scm[i]);
}

// ---------------- finalize: 4 matches per 256-thread block, W in smem ----------------
__global__ __launch_bounds__(256) void finalize_kernel(const float* __restrict__ kA,
                                                       const float* __restrict__ descA,
                                                       const float* __restrict__ kB,
                                                       const float* __restrict__ descB,
                                                       const float* __restrict__ W,
                                                       const float* __restrict__ bl,
                                                       float* __restrict__ out,
                                                       int b) {
    __shared__ float sw[ND0 * NK];  // 32 KB
    __shared__ float sa[4][256], sb_[4][256];
    __shared__ float red[4][2][7];

    int g = threadIdx.x >> 6;
    int t = threadIdx.x & 63;
    int gid = b * NN + blockIdx.x * 4 + g;

    for (int i = threadIdx.x * 4; i < ND0 * NK; i += 1024)
        *(float4*)(sw + i) = *(const float4*)(W + i);

    int j = g_rowj[gid];
    float Pij = g_rowP[gid];
    float cmj = __uint_as_float(g_colmaxP[b * NM + j]);
    bool valid = (Pij >= cmj) && (Pij > THRESH);

    const float* arow = descA + (size_t)gid * ND;
    const float* brow = descB + ((size_t)b * NM + j) * ND;
    *(float4*)(&sa[g][t * 4]) = *(const float4*)(arow + t * 4);
    *(float4*)(&sb_[g][t * 4]) = *(const float4*)(brow + t * 4);
    __syncthreads();

    float xA = 0.f, xB = 0.f;
#pragma unroll 8
    for (int d = 0; d < ND0; d++) {
        float wd = sw[d * NK + t];
        xA = fmaf(sa[g][d], wd, xA);
        xB = fmaf(sb_[g][d], wd, xB);
    }
    xA += __ldg(&bl[t]);
    xB += __ldg(&bl[t]);
    float spA = fmaxf(xA, 0.f) + log1pf(__expf(-fabsf(xA)));
    float spB = fmaxf(xB, 0.f) + log1pf(__expf(-fabsf(xB)));
    float wk = sqrtf(spA * spB);

    float x0 = sa[g][ND0 + 2 * t], x1 = sa[g][ND0 + 2 * t + 1];
    float y0 = sb_[g][ND0 + 2 * t], y1 = sb_[g][ND0 + 2 * t + 1];

    float vals[7];
    vals[0] = wk * x0 * x0;
    vals[1] = wk * x0 * x1;
    vals[2] = wk * x1 * x1;
    vals[3] = wk * y0 * x0;
    vals[4] = wk * y0 * x1;
    vals[5] = wk * y1 * x0;
    vals[6] = wk * y1 * x1;

#pragma unroll
    for (int i = 0; i < 7; i++) {
        float v = vals[i];
#pragma unroll
        for (int o = 16; o; o >>= 1) v += __shfl_xor_sync(0xffffffffu, v, o);
        if ((t & 31) == 0) red[g][t >> 5][i] = v;
    }
    __syncthreads();

    if (t == 0) {
        float g00 = red[g][0][0] + red[g][1][0] + EPS_G;
        float g01 = red[g][0][1] + red[g][1][1];
        float g11 = red[g][0][2] + red[g][1][2] + EPS_G;
        float c00 = red[g][0][3] + red[g][1][3];
        float c01 = red[g][0][4] + red[g][1][4];
        float c10 = red[g][0][5] + red[g][1][5];
        float c11 = red[g][0][6] + red[g][1][6];

        float dg = g00 * g11 - g01 * g01;
        float e00 = (c00 * g11 - c01 * g01) / dg;
        float e01 = (c01 * g00 - c00 * g01) / dg;
        float e10 = (c10 * g11 - c11 * g01) / dg;
        float e11 = (c11 * g00 - c10 * g01) / dg;

        float M00 = e00 * e00 + e10 * e10;
        float M01 = e00 * e01 + e10 * e11;
        float M11 = e01 * e01 + e11 * e11;
        float tr = M00 + M11;
        float dd = M00 * M11 - M01 * M01;
        float disc = sqrtf(fmaxf(0.25f * tr * tr - dd, 0.f));
        float shi = sqrtf(0.5f * tr + disc);
        float slo = sqrtf(fmaxf(0.5f * tr - disc, 0.f));

        bool good = isfinite(shi + slo) && (shi < 3.0f) && (slo > (1.0f / 3.0f));
        float dete = e00 * e11 - e01 * e10;
        good = good && (dete > 0.f);
        bool vfinal = valid && good;

        const int BN = NB * NN;
        out[(size_t)gid * 2 + 0] = kA[(size_t)gid * 2 + 0];
        out[(size_t)gid * 2 + 1] = kA[(size_t)gid * 2 + 1];
        out[(size_t)BN * 2 + (size_t)gid * 2 + 0] = kB[((size_t)b * NM + j) * 2 + 0];
        out[(size_t)BN * 2 + (size_t)gid * 2 + 1] = kB[((size_t)b * NM + j) * 2 + 1];
        out[(size_t)BN * 4 + gid] = (float)j;
        out[(size_t)BN * 5 + gid] = vfinal ? 1.0f : 0.0f;
    }
}

// ---------------- launch: proper capture fork/join, two streams ----------------
extern "C" void kernel_launch(void* const* d_in, const int* in_sizes, int n_in,
                              void* d_out, int out_size) {
    const float* kA = (const float*)d_in[0];
    const float* dA = (const float*)d_in[1];
    const float* kB = (const float*)d_in[2];
    const float* dB = (const float*)d_in[3];
    const float* W = (const float*)d_in[4];
    const float* bl = (const float*)d_in[5];
    float* out = (float*)d_out;

    static cudaStream_t s2;
    static cudaEvent_t ev0, evN, evA, evB, evD;
    static int inited = 0;
    if (!inited) {
        cudaFuncSetAttribute(gemm16_kernel,
                             cudaFuncAttributeMaxDynamicSharedMemorySize, GSMEM);
        cudaStreamCreateWithFlags(&s2, cudaStreamNonBlocking);
        cudaEventCreateWithFlags(&ev0, cudaEventDisableTiming);
        cudaEventCreateWithFlags(&evN, cudaEventDisableTiming);
        cudaEventCreateWithFlags(&evA, cudaEventDisableTiming);
        cudaEventCreateWithFlags(&evB, cudaEventDisableTiming);
        cudaEventCreateWithFlags(&evD, cudaEventDisableTiming);
        inited = 1;
    }

    // FORK: s2 joins the capture graph by waiting on an event from the origin stream
    cudaEventRecord(ev0, 0);
    cudaStreamWaitEvent(s2, ev0, 0);

    // side stream: normalize batches 2,3
    normalize_split_kernel<<<4 * NN, 256, 0, s2>>>(dA, dB, 2 * NN);
    cudaEventRecord(evN, s2);

    // main stream: normalize batches 0,1 then gemm(0,1)
    normalize_split_kernel<<<4 * NN, 256>>>(dA, dB, 0);
    dim3 g(NM / 128, NN / 128, 2);
    gemm16_kernel<<<g, 256, GSMEM>>>(0);
    cudaEventRecord(evA, 0);
    cudaStreamWaitEvent(0, evN, 0);
    gemm16_kernel<<<g, 256, GSMEM>>>(2);
    cudaEventRecord(evB, 0);

    // side stream: per-batch chains overlap gemm(2,3)
    cudaStreamWaitEvent(s2, evA, 0);
    for (int b = 0; b < 2; ++b) {
        reduce_sums_kernel<<<(2 * NN * 32) / 256, 256, 0, s2>>>(b);
        pmat_kernel<<<NN / 32, 256, 0, s2>>>(b);
        finalize_kernel<<<NN / 4, 256, 0, s2>>>(kA, dA, kB, dB, W, bl, out, b);
    }
    cudaStreamWaitEvent(s2, evB, 0);
    for (int b = 2; b < 4; ++b) {
        reduce_sums_kernel<<<(2 * NN * 32) / 256, 256, 0, s2>>>(b);
        pmat_kernel<<<NN / 32, 256, 0, s2>>>(b);
        finalize_kernel<<<NN / 4, 256, 0, s2>>>(kA, dA, kB, dB, W, bl, out, b);
    }
    cudaEventRecord(evD, s2);

    // JOIN: origin stream waits for the side chain
    cudaStreamWaitEvent(0, evD, 0);
}

// round 14
// speedup vs baseline: 1.1073x; 1.1073x over previous
#include <cuda_runtime.h>
#include <cuda_fp16.h>
#include <cuda_fp8.h>
#include <cstdint>
#include <math.h>

#define NB 4
#define NN 4096
#define NM 4096
#define ND 256
#define ND0 128
#define NK 64
#define GITERS 8            // 4 fp8 cross iters + 4 fp16 hi*hi iters (128B of K each)
#define THRESH 0.01f
#define EPS_G 1e-6f
#define LO_SCALE 131072.0f  // 2^17
#define HI_SCALE 16.0f      // 2^4
#define CROSS_INV (1.0f / (131072.0f * 16.0f))  // 2^-21
#define GSMEM (3 * 32768)   // 3 stages x (A 16KB + B 16KB)

// ---------------- scratch ----------------
static __device__ __align__(16) __half g_Ah[(size_t)NB * NN * 256];
static __device__ __align__(16) __half g_Bh[(size_t)NB * NM * 256];
static __device__ __align__(16) unsigned char g_Ax[(size_t)NB * NN * 512];
static __device__ __align__(16) unsigned char g_Bx[(size_t)NB * NM * 512];
static __device__ float g_sim[(size_t)NB * NN * NM];   // holds e = exp(sim)
static __device__ float g_rowinv[NB * NN];
static __device__ float g_colinv[NB * NM];
static __device__ float g_rowsum_part[NB * NN * 32];
static __device__ float g_colsum_part[NB * NM * 32];
static __device__ int g_rowj[NB * NN];
static __device__ float g_rowP[NB * NN];
static __device__ unsigned g_colmaxP[NB * NM];

__device__ __forceinline__ uint32_t smem_to_u32(const void* p) {
    uint32_t a;
    asm("{ .reg .u64 t; cvta.to.shared.u64 t, %1; cvt.u32.u64 %0, t; }" : "=r"(a) : "l"(p));
    return a;
}

// CUTLASS-style crosswise swizzle for 64B rows: 16B group XOR (row & 3)
__device__ __forceinline__ uint32_t swz(uint32_t r, uint32_t bytecol) {
    return r * 64 + ((((bytecol >> 4) & 3) ^ (r & 3)) << 4) + (bytecol & 15);
}

__device__ __forceinline__ void cpasync16(uint32_t dst, const void* src) {
    asm volatile("cp.async.cg.shared.global [%0], [%1], 16;" :: "r"(dst), "l"(src));
}

__device__ __forceinline__ void ldsm4(uint32_t& d0, uint32_t& d1, uint32_t& d2, uint32_t& d3,
                                      uint32_t addr) {
    asm volatile("ldmatrix.sync.aligned.m8n8.x4.shared.b16 {%0,%1,%2,%3}, [%4];"
                 : "=r"(d0), "=r"(d1), "=r"(d2), "=r"(d3) : "r"(addr));
}

__device__ __forceinline__ void mma16816(float* c, const uint32_t* a, const uint32_t* b) {
    asm volatile(
        "mma.sync.aligned.m16n8k16.row.col.f32.f16.f16.f32 "
        "{%0,%1,%2,%3}, {%4,%5,%6,%7}, {%8,%9}, {%0,%1,%2,%3};"
        : "+f"(c[0]), "+f"(c[1]), "+f"(c[2]), "+f"(c[3])
        : "r"(a[0]), "r"(a[1]), "r"(a[2]), "r"(a[3]), "r"(b[0]), "r"(b[1]));
}

__device__ __forceinline__ void mma16832q(float* c, const uint32_t* a, const uint32_t* b) {
    asm volatile(
        "mma.sync.aligned.m16n8k32.row.col.f32.e4m3.e4m3.f32 "
        "{%0,%1,%2,%3}, {%4,%5,%6,%7}, {%8,%9}, {%0,%1,%2,%3};"
        : "+f"(c[0]), "+f"(c[1]), "+f"(c[2]), "+f"(c[3])
        : "r"(a[0]), "r"(a[1]), "r"(a[2]), "r"(a[3]), "r"(b[0]), "r"(b[1]));
}

// ---------------- normalize + split (init folded in) ----------------
__global__ void normalize_split_kernel(const float* __restrict__ descA,
                                       const float* __restrict__ descB) {
    int row = blockIdx.x;  // 0 .. 2*NB*NN-1
    bool isA = row < NB * NN;
    if (isA && threadIdx.x == 0) g_colmaxP[row] = 0u;
    int r = isA ? row : row - NB * NN;
    const float* src = (isA ? descA : descB) + (size_t)r * ND;
    int t = threadIdx.x;  // 256
    float v = src[t];
    float s = v * v;
#pragma unroll
    for (int o = 16; o; o >>= 1) s += __shfl_xor_sync(0xffffffffu, s, o);
    __shared__ float ws[8];
    if ((t & 31) == 0) ws[t >> 5] = s;
    __syncthreads();
    float tot = ws[0] + ws[1] + ws[2] + ws[3] + ws[4] + ws[5] + ws[6] + ws[7];
    float nv = v / sqrtf(tot);
    __half hi = __float2half_rn(nv);
    float lof = (nv - __half2float(hi)) * LO_SCALE;
    float hif = nv * HI_SCALE;
    unsigned char loq = (unsigned char)__nv_cvt_float_to_fp8(lof, __NV_SATFINITE, __NV_E4M3);
    unsigned char hiq = (unsigned char)__nv_cvt_float_to_fp8(hif, __NV_SATFINITE, __NV_E4M3);
    if (isA) {
        g_Ah[(size_t)r * 256 + t] = hi;
        g_Ax[(size_t)r * 512 + t] = loq;        // A cross = [lo' | hi']
        g_Ax[(size_t)r * 512 + 256 + t] = hiq;
    } else {
        g_Bh[(size_t)r * 256 + t] = hi;
        g_Bx[(size_t)r * 512 + t] = hiq;        // B cross = [hi' | lo']
        g_Bx[(size_t)r * 512 + 256 + t] = loq;
    }
}

// ---------------- GEMM (R10 config + warp-staggered ks) ----------------
__global__ __launch_bounds__(256, 2) void gemm16_kernel() {
    extern __shared__ __align__(128) char buf[];

    int tid = threadIdx.x, lane = tid & 31, wid = tid >> 5;
    int warp_m = wid & 1;
    int warp_n = wid >> 1;
    int b = blockIdx.z;
    int m0 = blockIdx.x * 128;
    int n0 = blockIdx.y * 128;
    uint32_t sbase = smem_to_u32(buf);
    int kstag = (wid & 1) * 2;   // odd warps start at ks=2

    int lr = tid >> 1;
    int ls = (tid & 1) * 2;

    const char* Agx = (const char*)g_Ax + ((size_t)b * NN + n0 + lr) * 512 + ls * 16;
    const char* Bgx = (const char*)g_Bx + ((size_t)b * NM + m0 + lr) * 512 + ls * 16;
    const char* Agh = (const char*)g_Ah + ((size_t)b * NN + n0 + lr) * 512 + ls * 16;
    const char* Bgh = (const char*)g_Bh + ((size_t)b * NM + m0 + lr) * 512 + ls * 16;

    uint32_t pf0 = swz((uint32_t)lr, (uint32_t)ls * 16);
    uint32_t pf1 = swz((uint32_t)lr, (uint32_t)(ls + 1) * 16);

    uint32_t offA[2][4], offB[2][2];
#pragma unroll
    for (int ks = 0; ks < 2; ++ks) {
#pragma unroll
        for (int mf = 0; mf < 4; ++mf)
            offA[ks][mf] = swz(warp_m * 64 + mf * 16 + (lane & 15),
                               ks * 32 + (lane >> 4) * 16);
#pragma unroll
        for (int np = 0; np < 2; ++np)
            offB[ks][np] = swz(warp_n * 32 + np * 16 + (lane & 7) + ((lane >> 4) << 3),
                               ks * 32 + ((lane >> 3) & 1) * 16);
    }

    auto prefetch = [&](int it2) {
        int slot = it2 % 3;
        const char *Ab_, *Bb_;
        if (it2 < 4) { Ab_ = Agx + it2 * 128; Bb_ = Bgx + it2 * 128; }
        else         { Ab_ = Agh + (it2 - 4) * 128; Bb_ = Bgh + (it2 - 4) * 128; }
        uint32_t as_ = sbase + slot * 32768;
        uint32_t bs_ = as_ + 16384;
        cpasync16(as_ + pf0, Ab_);
        cpasync16(as_ + pf1, Ab_ + 16);
        cpasync16(as_ + 8192 + pf0, Ab_ + 64);
        cpasync16(as_ + 8192 + pf1, Ab_ + 80);
        cpasync16(bs_ + pf0, Bb_);
        cpasync16(bs_ + pf1, Bb_ + 16);
        cpasync16(bs_ + 8192 + pf0, Bb_ + 64);
        cpasync16(bs_ + 8192 + pf1, Bb_ + 80);
        asm volatile("cp.async.commit_group;" ::: "memory");
    };

    prefetch(0);
    prefetch(1);

    float acc[4][4][4];
#pragma unroll
    for (int i = 0; i < 4; i++)
#pragma unroll
        for (int j = 0; j < 4; j++)
#pragma unroll
            for (int k = 0; k < 4; k++) acc[i][j][k] = 0.f;

    // ---- phase 1: cross terms, fp8 e4m3 ----
#pragma unroll 1
    for (int it = 0; it < 4; ++it) {
        if (it < GITERS - 2) {
            asm volatile("cp.async.wait_group 1;" ::: "memory");
        } else {
            asm volatile("cp.async.wait_group 0;" ::: "memory");
        }
        __syncthreads();
        if (it + 2 < GITERS) prefetch(it + 2);

        int slot = it % 3;
        uint32_t ab0 = sbase + slot * 32768;
        uint32_t bb0 = ab0 + 16384;
#pragma unroll
        for (int kss = 0; kss < 4; ++kss) {
            int ks = (kss + kstag) & 3;
            uint32_t ab = ab0 + (ks >> 1) * 8192, bb = bb0 + (ks >> 1) * 8192;
            int kl = ks & 1;
            uint32_t a[4][4];
#pragma unroll
            for (int mf = 0; mf < 4; ++mf)
                ldsm4(a[mf][0], a[mf][1], a[mf][2], a[mf][3], ab + offA[kl][mf]);
            uint32_t bf[4][2];
#pragma unroll
            for (int np = 0; np < 2; ++np) {
                uint32_t r0, r1, r2, r3;
                ldsm4(r0, r1, r2, r3, bb + offB[kl][np]);
                bf[np * 2][0] = r0; bf[np * 2][1] = r1;
                bf[np * 2 + 1][0] = r2; bf[np * 2 + 1][1] = r3;
            }
#pragma unroll
            for (int mf = 0; mf < 4; ++mf)
#pragma unroll
                for (int nf = 0; nf < 4; ++nf) mma16832q(acc[mf][nf], a[mf], bf[nf]);
        }
    }

    // ---- scale cross contribution ----
#pragma unroll
    for (int mf = 0; mf < 4; ++mf)
#pragma unroll
        for (int nf = 0; nf < 4; ++nf)
#pragma unroll
            for (int k = 0; k < 4; ++k) acc[mf][nf][k] *= CROSS_INV;

    // ---- phase 2: hi*hi, fp16 fp32-acc ----
#pragma unroll 1
    for (int it = 4; it < 8; ++it) {
        if (it < GITERS - 2) {
            asm volatile("cp.async.wait_group 1;" ::: "memory");
        } else {
            asm volatile("cp.async.wait_group 0;" ::: "memory");
        }
        __syncthreads();
        if (it + 2 < GITERS) prefetch(it + 2);

        int slot = it % 3;
        uint32_t ab0 = sbase + slot * 32768;
        uint32_t bb0 = ab0 + 16384;
#pragma unroll
        for (int kss = 0; kss < 4; ++kss) {
            int ks = (kss + kstag) & 3;
            uint32_t ab = ab0 + (ks >> 1) * 8192, bb = bb0 + (ks >> 1) * 8192;
            int kl = ks & 1;
            uint32_t a[4][4];
#pragma unroll
            for (int mf = 0; mf < 4; ++mf)
                ldsm4(a[mf][0], a[mf][1], a[mf][2], a[mf][3], ab + offA[kl][mf]);
            uint32_t bf[4][2];
#pragma unroll
            for (int np = 0; np < 2; ++np) {
                uint32_t r0, r1, r2, r3;
                ldsm4(r0, r1, r2, r3, bb + offB[kl][np]);
                bf[np * 2][0] = r0; bf[np * 2][1] = r1;
                bf[np * 2 + 1][0] = r2; bf[np * 2 + 1][1] = r3;
            }
#pragma unroll
            for (int mf = 0; mf < 4; ++mf)
#pragma unroll
                for (int nf = 0; nf < 4; ++nf) mma16816(acc[mf][nf], a[mf], bf[nf]);
        }
    }
    __syncthreads();  // compute done; reuse buf as reduction scratch

    float (*rowred)[4] = (float(*)[4])buf;
    float (*colred)[2] = (float(*)[2])(buf + 2048);

    // ---------- epilogue: e = __expf(20*acc), streaming store, partial sums ----------
    int qt = lane >> 2;
    int qc = lane & 3;
    float rsl[4][2];
    float csl[4][2];
#pragma unroll
    for (int i = 0; i < 4; i++) { rsl[i][0] = rsl[i][1] = 0.f; csl[i][0] = csl[i][1] = 0.f; }

    float* S = g_sim + (size_t)b * NN * NM;
#pragma unroll
    for (int mf = 0; mf < 4; ++mf) {
#pragma unroll
        for (int h = 0; h < 2; ++h) {
            int gr = n0 + warp_m * 64 + mf * 16 + qt + 8 * h;
            float* Sr = S + (size_t)gr * NM + m0 + warp_n * 32;
#pragma unroll
            for (int nf = 0; nf < 4; ++nf) {
                float e0 = __expf(20.0f * acc[mf][nf][h * 2 + 0]);
                float e1 = __expf(20.0f * acc[mf][nf][h * 2 + 1]);
                __stcs((float2*)(Sr + nf * 8 + qc * 2), make_float2(e0, e1));
                rsl[mf][h] += e0 + e1;
                csl[nf][0] += e0;
                csl[nf][1] += e1;
            }
        }
    }

#pragma unroll
    for (int mf = 0; mf < 4; ++mf)
#pragma unroll
        for (int h = 0; h < 2; ++h) {
            float v = rsl[mf][h];
            v += __shfl_xor_sync(0xffffffffu, v, 1);
            v += __shfl_xor_sync(0xffffffffu, v, 2);
            if (qc == 0) rowred[warp_m * 64 + mf * 16 + qt + 8 * h][warp_n] = v;
        }
#pragma unroll
    for (int nf = 0; nf < 4; ++nf)
#pragma unroll
        for (int c = 0; c < 2; ++c) {
            float v = csl[nf][c];
            v += __shfl_xor_sync(0xffffffffu, v, 4);
            v += __shfl_xor_sync(0xffffffffu, v, 8);
            v += __shfl_xor_sync(0xffffffffu, v, 16);
            if (qt == 0) colred[warp_n * 32 + nf * 8 + qc * 2 + c][warp_m] = v;
        }
    __syncthreads();

    if (tid < 128) {
        float rv = rowred[tid][0] + rowred[tid][1] + rowred[tid][2] + rowred[tid][3];
        g_rowsum_part[((size_t)b * NN + n0 + tid) * 32 + blockIdx.x] = rv;
        float cv = colred[tid][0] + colred[tid][1];
        g_colsum_part[((size_t)b * NM + m0 + tid) * 32 + blockIdx.y] = cv;
    }
}

// ---------------- final sum reduction -> reciprocals ----------------
__global__ void reduce_sums_kernel() {
    int warp = (blockIdx.x * blockDim.x + threadIdx.x) >> 5;  // 0..32767
    int lane = threadIdx.x & 31;
    if (warp < NB * NN) {
        float v = g_rowsum_part[warp * 32 + lane];
#pragma unroll
        for (int o = 16; o; o >>= 1) v += __shfl_xor_sync(0xffffffffu, v, o);
        if (lane == 0) g_rowinv[warp] = 1.0f / v;
    } else {
        int k = warp - NB * NN;
        float v = g_colsum_part[k * 32 + lane];
#pragma unroll
        for (int o = 16; o; o >>= 1) v += __shfl_xor_sync(0xffffffffu, v, o);
        if (lane == 0) g_colinv[k] = 1.0f / v;
    }
}

// ---------------- P pass: warp-per-4-rows, shared colmax ----------------
__global__ __launch_bounds__(256) void pmat_kernel() {
    __shared__ unsigned scm[NM];  // 16 KB column max of p
    int b = blockIdx.y;
    int tid = threadIdx.x, lane = tid & 31, w = tid >> 5;
    int row0 = blockIdx.x * 32 + w * 4;
    const float* S = g_sim + (size_t)b * NN * NM + (size_t)row0 * NM;
    const float* CI = g_colinv + b * NM;

    for (int i = tid; i < NM; i += 256) scm[i] = 0u;

    float ri[4];
#pragma unroll
    for (int r = 0; r < 4; ++r) ri[r] = __ldg(&g_rowinv[b * NN + row0 + r]);

    __syncthreads();

    float best[4] = {-1.f, -1.f, -1.f, -1.f};
    int bm[4] = {0, 0, 0, 0};

#pragma unroll 1
    for (int k = 0; k < 32; ++k) {
        int c = k * 128 + lane * 4;
        float4 civ = __ldg((const float4*)(CI + c));
        float cm[4] = {0.f, 0.f, 0.f, 0.f};
#pragma unroll
        for (int r = 0; r < 4; ++r) {
            float4 e = __ldcs((const float4*)(S + (size_t)r * NM + c));
            float q0 = (e.x * e.x) * civ.x;
            float q1 = (e.y * e.y) * civ.y;
            float q2 = (e.z * e.z) * civ.z;
            float q3 = (e.w * e.w) * civ.w;
            if (q0 > best[r]) { best[r] = q0; bm[r] = c; }
            if (q1 > best[r]) { best[r] = q1; bm[r] = c + 1; }
            if (q2 > best[r]) { best[r] = q2; bm[r] = c + 2; }
            if (q3 > best[r]) { best[r] = q3; bm[r] = c + 3; }
            cm[0] = fmaxf(cm[0], q0 * ri[r]);
            cm[1] = fmaxf(cm[1], q1 * ri[r]);
            cm[2] = fmaxf(cm[2], q2 * ri[r]);
            cm[3] = fmaxf(cm[3], q3 * ri[r]);
        }
        atomicMax(&scm[c + 0], __float_as_uint(cm[0]));
        atomicMax(&scm[c + 1], __float_as_uint(cm[1]));
        atomicMax(&scm[c + 2], __float_as_uint(cm[2]));
        atomicMax(&scm[c + 3], __float_as_uint(cm[3]));
    }

#pragma unroll
    for (int r = 0; r < 4; ++r) {
        float bq = best[r];
        int bj = bm[r];
#pragma unroll
        for (int o = 16; o; o >>= 1) {
            float ob = __shfl_xor_sync(0xffffffffu, bq, o);
            int obj = __shfl_xor_sync(0xffffffffu, bj, o);
            if (ob > bq || (ob == bq && obj < bj)) { bq = ob; bj = obj; }
        }
        if (lane == 0) {
            g_rowj[b * NN + row0 + r] = bj;
            g_rowP[b * NN + row0 + r] = bq * ri[r];
        }
    }

    __syncthreads();
    for (int i = tid; i < NM; i += 256)
        atomicMax(&g_colmaxP[b * NM + i], scm[i]);
}

// ---------------- finalize: 8 matches per 512-thread block, W in smem ----------------
__global__ __launch_bounds__(512) void finalize_kernel(const float* __restrict__ kA,
                                                       const float* __restrict__ descA,
                                                       const float* __restrict__ kB,
                                                       const float* __restrict__ descB,
                                                       const float* __restrict__ W,
                                                       const float* __restrict__ bl,
                                                       float* __restrict__ out) {
    __shared__ float sw[ND0 * NK];  // 32 KB
    __shared__ float sa[8][256], sb_[8][256];
    __shared__ float red[8][2][7];

    int g = threadIdx.x >> 6;          // match group 0..7
    int t = threadIdx.x & 63;
    int gid = blockIdx.x * 8 + g;
    int b = gid >> 12;

    for (int i = threadIdx.x * 4; i < ND0 * NK; i += 2048)
        *(float4*)(sw + i) = *(const float4*)(W + i);

    int j = g_rowj[gid];
    float Pij = g_rowP[gid];
    float cmj = __uint_as_float(g_colmaxP[b * NM + j]);
    bool valid = (Pij >= cmj) && (Pij > THRESH);

    const float* arow = descA + (size_t)gid * ND;
    const float* brow = descB + ((size_t)b * NM + j) * ND;
    *(float4*)(&sa[g][t * 4]) = *(const float4*)(arow + t * 4);
    *(float4*)(&sb_[g][t * 4]) = *(const float4*)(brow + t * 4);
    __syncthreads();

    float xA = 0.f, xB = 0.f;
#pragma unroll 8
    for (int d = 0; d < ND0; d++) {
        float wd = sw[d * NK + t];
        xA = fmaf(sa[g][d], wd, xA);
        xB = fmaf(sb_[g][d], wd, xB);
    }
    xA += __ldg(&bl[t]);
    xB += __ldg(&bl[t]);
    float spA = fmaxf(xA, 0.f) + log1pf(__expf(-fabsf(xA)));
    float spB = fmaxf(xB, 0.f) + log1pf(__expf(-fabsf(xB)));
    float wk = sqrtf(spA * spB);

    float x0 = sa[g][ND0 + 2 * t], x1 = sa[g][ND0 + 2 * t + 1];
    float y0 = sb_[g][ND0 + 2 * t], y1 = sb_[g][ND0 + 2 * t + 1];

    float vals[7];
    vals[0] = wk * x0 * x0;
    vals[1] = wk * x0 * x1;
    vals[2] = wk * x1 * x1;
    vals[3] = wk * y0 * x0;
    vals[4] = wk * y0 * x1;
    vals[5] = wk * y1 * x0;
    vals[6] = wk * y1 * x1;

#pragma unroll
    for (int i = 0; i < 7; i++) {
        float v = vals[i];
#pragma unroll
        for (int o = 16; o; o >>= 1) v += __shfl_xor_sync(0xffffffffu, v, o);
        if ((t & 31) == 0) red[g][t >> 5][i] = v;
    }
    __syncthreads();

    if (t == 0) {
        float g00 = red[g][0][0] + red[g][1][0] + EPS_G;
        float g01 = red[g][0][1] + red[g][1][1];
        float g11 = red[g][0][2] + red[g][1][2] + EPS_G;
        float c00 = red[g][0][3] + red[g][1][3];
        float c01 = red[g][0][4] + red[g][1][4];
        float c10 = red[g][0][5] + red[g][1][5];
        float c11 = red[g][0][6] + red[g][1][6];

        float dg = g00 * g11 - g01 * g01;
        float e00 = (c00 * g11 - c01 * g01) / dg;
        float e01 = (c01 * g00 - c00 * g01) / dg;
        float e10 = (c10 * g11 - c11 * g01) / dg;
        float e11 = (c11 * g00 - c10 * g01) / dg;

        float M00 = e00 * e00 + e10 * e10;
        float M01 = e00 * e01 + e10 * e11;
        float M11 = e01 * e01 + e11 * e11;
        float tr = M00 + M11;
        float dd = M00 * M11 - M01 * M01;
        float disc = sqrtf(fmaxf(0.25f * tr * tr - dd, 0.f));
        float shi = sqrtf(0.5f * tr + disc);
        float slo = sqrtf(fmaxf(0.5f * tr - disc, 0.f));

        bool good = isfinite(shi + slo) && (shi < 3.0f) && (slo > (1.0f / 3.0f));
        float dete = e00 * e11 - e01 * e10;
        good = good && (dete > 0.f);
        bool vfinal = valid && good;

        const int BN = NB * NN;
        out[(size_t)gid * 2 + 0] = kA[(size_t)gid * 2 + 0];
        out[(size_t)gid * 2 + 1] = kA[(size_t)gid * 2 + 1];
        out[(size_t)BN * 2 + (size_t)gid * 2 + 0] = kB[((size_t)b * NM + j) * 2 + 0];
        out[(size_t)BN * 2 + (size_t)gid * 2 + 1] = kB[((size_t)b * NM + j) * 2 + 1];
        out[(size_t)BN * 4 + gid] = (float)j;
        out[(size_t)BN * 5 + gid] = vfinal ? 1.0f : 0.0f;
    }
}

// ---------------- launch (single stream, R10 schedule) ----------------
extern "C" void kernel_launch(void* const* d_in, const int* in_sizes, int n_in,
                              void* d_out, int out_size) {
    const float* kA = (const float*)d_in[0];
    const float* dA = (const float*)d_in[1];
    const float* kB = (const float*)d_in[2];
    const float* dB = (const float*)d_in[3];
    const float* W = (const float*)d_in[4];
    const float* bl = (const float*)d_in[5];
    float* out = (float*)d_out;

    static int attr_set = 0;
    if (!attr_set) {
        cudaFuncSetAttribute(gemm16_kernel,
                             cudaFuncAttributeMaxDynamicSharedMemorySize, GSMEM);
        attr_set = 1;
    }

    normalize_split_kernel<<<2 * NB * NN, 256>>>(dA, dB);

    dim3 g(NM / 128, NN / 128, NB);
    gemm16_kernel<<<g, 256, GSMEM>>>();
    reduce_sums_kernel<<<(2 * NB * NN * 32 + 255) / 256, 256>>>();
    pmat_kernel<<<dim3(NN / 32, NB), 256>>>();
    finalize_kernel<<<NB * NN / 8, 512>>>(kA, dA, kB, dB, W, bl, out);
}

// round 15
// speedup vs baseline: 1.1905x; 1.0752x over previous
#include <cuda_runtime.h>
#include <cuda_fp16.h>
#include <cuda_fp8.h>
#include <cstdint>
#include <math.h>

#define NB 4
#define NN 4096
#define NM 4096
#define ND 256
#define ND0 128
#define NK 64
#define GITERS 8            // 4 fp8 cross iters + 4 fp16 hi*hi iters (128B of K each)
#define THRESH 0.01f
#define EPS_G 1e-6f
#define LO_SCALE 131072.0f  // 2^17
#define HI_SCALE 16.0f      // 2^4
#define CROSS_INV (1.0f / (131072.0f * 16.0f))  // 2^-21
#define GSMEM (3 * 32768)   // 3 stages x (A 16KB + B 16KB)

// ---------------- scratch ----------------
static __device__ __align__(16) __half g_Ah[(size_t)NB * NN * 256];
static __device__ __align__(16) __half g_Bh[(size_t)NB * NM * 256];
static __device__ __align__(16) unsigned char g_Ax[(size_t)NB * NN * 512];
static __device__ __align__(16) unsigned char g_Bx[(size_t)NB * NM * 512];
static __device__ float g_sim[(size_t)NB * NN * NM];   // holds e = exp(sim)
static __device__ float g_rowinv[NB * NN];
static __device__ float g_colinv[NB * NM];
static __device__ float g_rowsum_part[NB * NN * 32];
static __device__ float g_colsum_part[NB * NM * 32];
static __device__ int g_rowj[NB * NN];
static __device__ float g_rowP[NB * NN];
static __device__ unsigned g_colmaxP[NB * NM];

__device__ __forceinline__ uint32_t smem_to_u32(const void* p) {
    uint32_t a;
    asm("{ .reg .u64 t; cvta.to.shared.u64 t, %1; cvt.u32.u64 %0, t; }" : "=r"(a) : "l"(p));
    return a;
}

// CUTLASS-style crosswise swizzle for 64B rows: 16B group XOR (row & 3)
__device__ __forceinline__ uint32_t swz(uint32_t r, uint32_t bytecol) {
    return r * 64 + ((((bytecol >> 4) & 3) ^ (r & 3)) << 4) + (bytecol & 15);
}

__device__ __forceinline__ void cpasync16(uint32_t dst, const void* src) {
    asm volatile("cp.async.cg.shared.global [%0], [%1], 16;" :: "r"(dst), "l"(src));
}

__device__ __forceinline__ void ldsm4(uint32_t& d0, uint32_t& d1, uint32_t& d2, uint32_t& d3,
                                      uint32_t addr) {
    asm volatile("ldmatrix.sync.aligned.m8n8.x4.shared.b16 {%0,%1,%2,%3}, [%4];"
                 : "=r"(d0), "=r"(d1), "=r"(d2), "=r"(d3) : "r"(addr));
}

__device__ __forceinline__ void mma16816(float* c, const uint32_t* a, const uint32_t* b) {
    asm volatile(
        "mma.sync.aligned.m16n8k16.row.col.f32.f16.f16.f32 "
        "{%0,%1,%2,%3}, {%4,%5,%6,%7}, {%8,%9}, {%0,%1,%2,%3};"
        : "+f"(c[0]), "+f"(c[1]), "+f"(c[2]), "+f"(c[3])
        : "r"(a[0]), "r"(a[1]), "r"(a[2]), "r"(a[3]), "r"(b[0]), "r"(b[1]));
}

__device__ __forceinline__ void mma16832q(float* c, const uint32_t* a, const uint32_t* b) {
    asm volatile(
        "mma.sync.aligned.m16n8k32.row.col.f32.e4m3.e4m3.f32 "
        "{%0,%1,%2,%3}, {%4,%5,%6,%7}, {%8,%9}, {%0,%1,%2,%3};"
        : "+f"(c[0]), "+f"(c[1]), "+f"(c[2]), "+f"(c[3])
        : "r"(a[0]), "r"(a[1]), "r"(a[2]), "r"(a[3]), "r"(b[0]), "r"(b[1]));
}

// ---------------- normalize + split v2: 4 rows per 256-thread block ----------------
__global__ void normalize_split_kernel(const float* __restrict__ descA,
                                       const float* __restrict__ descB) {
    int g = threadIdx.x >> 6;          // row group 0..3
    int tc = threadIdx.x & 63;         // 64 threads per row
    int c4 = tc * 4;
    int row = blockIdx.x * 4 + g;      // 0..32767
    bool isA = row < NB * NN;
    int r = isA ? row : row - NB * NN;
    if (isA && tc == 0) g_colmaxP[row] = 0u;

    const float* src = (isA ? descA : descB) + (size_t)r * ND + c4;
    float4 v = *(const float4*)src;
    float s = v.x * v.x + v.y * v.y + v.z * v.z + v.w * v.w;
#pragma unroll
    for (int o = 16; o; o >>= 1) s += __shfl_xor_sync(0xffffffffu, s, o);
    __shared__ float ws[8];
    if ((threadIdx.x & 31) == 0) ws[threadIdx.x >> 5] = s;
    __syncthreads();
    float sq = sqrtf(ws[2 * g] + ws[2 * g + 1]);

    float nv[4] = {v.x / sq, v.y / sq, v.z / sq, v.w / sq};
    __half hh[4];
    uchar4 lo4, hi4;
    unsigned char* lop = (unsigned char*)&lo4;
    unsigned char* hip = (unsigned char*)&hi4;
#pragma unroll
    for (int i = 0; i < 4; ++i) {
        __half hi = __float2half_rn(nv[i]);
        hh[i] = hi;
        float lof = (nv[i] - __half2float(hi)) * LO_SCALE;
        float hif = nv[i] * HI_SCALE;
        lop[i] = (unsigned char)__nv_cvt_float_to_fp8(lof, __NV_SATFINITE, __NV_E4M3);
        hip[i] = (unsigned char)__nv_cvt_float_to_fp8(hif, __NV_SATFINITE, __NV_E4M3);
    }

    if (isA) {
        *(uint2*)(g_Ah + (size_t)r * 256 + c4) = *(uint2*)hh;
        *(uchar4*)(g_Ax + (size_t)r * 512 + c4) = lo4;          // A cross = [lo' | hi']
        *(uchar4*)(g_Ax + (size_t)r * 512 + 256 + c4) = hi4;
    } else {
        *(uint2*)(g_Bh + (size_t)r * 256 + c4) = *(uint2*)hh;
        *(uchar4*)(g_Bx + (size_t)r * 512 + c4) = hi4;          // B cross = [hi' | lo']
        *(uchar4*)(g_Bx + (size_t)r * 512 + 256 + c4) = lo4;
    }
}

// ---------------- GEMM (exact R10): 128x128 tile, 8 warps, 3-stage x 32KB ----------------
__global__ __launch_bounds__(256, 2) void gemm16_kernel() {
    extern __shared__ __align__(128) char buf[];

    int tid = threadIdx.x, lane = tid & 31, wid = tid >> 5;
    int warp_m = wid & 1;
    int warp_n = wid >> 1;
    int b = blockIdx.z;
    int m0 = blockIdx.x * 128;
    int n0 = blockIdx.y * 128;
    uint32_t sbase = smem_to_u32(buf);

    int lr = tid >> 1;
    int ls = (tid & 1) * 2;

    const char* Agx = (const char*)g_Ax + ((size_t)b * NN + n0 + lr) * 512 + ls * 16;
    const char* Bgx = (const char*)g_Bx + ((size_t)b * NM + m0 + lr) * 512 + ls * 16;
    const char* Agh = (const char*)g_Ah + ((size_t)b * NN + n0 + lr) * 512 + ls * 16;
    const char* Bgh = (const char*)g_Bh + ((size_t)b * NM + m0 + lr) * 512 + ls * 16;

    uint32_t pf0 = swz((uint32_t)lr, (uint32_t)ls * 16);
    uint32_t pf1 = swz((uint32_t)lr, (uint32_t)(ls + 1) * 16);

    uint32_t offA[2][4], offB[2][2];
#pragma unroll
    for (int ks = 0; ks < 2; ++ks) {
#pragma unroll
        for (int mf = 0; mf < 4; ++mf)
            offA[ks][mf] = swz(warp_m * 64 + mf * 16 + (lane & 15),
                               ks * 32 + (lane >> 4) * 16);
#pragma unroll
        for (int np = 0; np < 2; ++np)
            offB[ks][np] = swz(warp_n * 32 + np * 16 + (lane & 7) + ((lane >> 4) << 3),
                               ks * 32 + ((lane >> 3) & 1) * 16);
    }

    auto prefetch = [&](int it2) {
        int slot = it2 % 3;
        const char *Ab_, *Bb_;
        if (it2 < 4) { Ab_ = Agx + it2 * 128; Bb_ = Bgx + it2 * 128; }
        else         { Ab_ = Agh + (it2 - 4) * 128; Bb_ = Bgh + (it2 - 4) * 128; }
        uint32_t as_ = sbase + slot * 32768;
        uint32_t bs_ = as_ + 16384;
        cpasync16(as_ + pf0, Ab_);
        cpasync16(as_ + pf1, Ab_ + 16);
        cpasync16(as_ + 8192 + pf0, Ab_ + 64);
        cpasync16(as_ + 8192 + pf1, Ab_ + 80);
        cpasync16(bs_ + pf0, Bb_);
        cpasync16(bs_ + pf1, Bb_ + 16);
        cpasync16(bs_ + 8192 + pf0, Bb_ + 64);
        cpasync16(bs_ + 8192 + pf1, Bb_ + 80);
        asm volatile("cp.async.commit_group;" ::: "memory");
    };

    prefetch(0);
    prefetch(1);

    float acc[4][4][4];
#pragma unroll
    for (int i = 0; i < 4; i++)
#pragma unroll
        for (int j = 0; j < 4; j++)
#pragma unroll
            for (int k = 0; k < 4; k++) acc[i][j][k] = 0.f;

    // ---- phase 1: cross terms, fp8 e4m3 ----
#pragma unroll 1
    for (int it = 0; it < 4; ++it) {
        if (it < GITERS - 2) {
            asm volatile("cp.async.wait_group 1;" ::: "memory");
        } else {
            asm volatile("cp.async.wait_group 0;" ::: "memory");
        }
        __syncthreads();
        if (it + 2 < GITERS) prefetch(it + 2);

        int slot = it % 3;
        uint32_t ab0 = sbase + slot * 32768;
        uint32_t bb0 = ab0 + 16384;
#pragma unroll
        for (int ks = 0; ks < 4; ++ks) {
            uint32_t ab = ab0 + (ks >> 1) * 8192, bb = bb0 + (ks >> 1) * 8192;
            int kl = ks & 1;
            uint32_t a[4][4];
#pragma unroll
            for (int mf = 0; mf < 4; ++mf)
                ldsm4(a[mf][0], a[mf][1], a[mf][2], a[mf][3], ab + offA[kl][mf]);
            uint32_t bf[4][2];
#pragma unroll
            for (int np = 0; np < 2; ++np) {
                uint32_t r0, r1, r2, r3;
                ldsm4(r0, r1, r2, r3, bb + offB[kl][np]);
                bf[np * 2][0] = r0; bf[np * 2][1] = r1;
                bf[np * 2 + 1][0] = r2; bf[np * 2 + 1][1] = r3;
            }
#pragma unroll
            for (int mf = 0; mf < 4; ++mf)
#pragma unroll
                for (int nf = 0; nf < 4; ++nf) mma16832q(acc[mf][nf], a[mf], bf[nf]);
        }
    }

    // ---- scale cross contribution ----
#pragma unroll
    for (int mf = 0; mf < 4; ++mf)
#pragma unroll
        for (int nf = 0; nf < 4; ++nf)
#pragma unroll
            for (int k = 0; k < 4; ++k) acc[mf][nf][k] *= CROSS_INV;

    // ---- phase 2: hi*hi, fp16 fp32-acc ----
#pragma unroll 1
    for (int it = 4; it < 8; ++it) {
        if (it < GITERS - 2) {
            asm volatile("cp.async.wait_group 1;" ::: "memory");
        } else {
            asm volatile("cp.async.wait_group 0;" ::: "memory");
        }
        __syncthreads();
        if (it + 2 < GITERS) prefetch(it + 2);

        int slot = it % 3;
        uint32_t ab0 = sbase + slot * 32768;
        uint32_t bb0 = ab0 + 16384;
#pragma unroll
        for (int ks = 0; ks < 4; ++ks) {
            uint32_t ab = ab0 + (ks >> 1) * 8192, bb = bb0 + (ks >> 1) * 8192;
            int kl = ks & 1;
            uint32_t a[4][4];
#pragma unroll
            for (int mf = 0; mf < 4; ++mf)
                ldsm4(a[mf][0], a[mf][1], a[mf][2], a[mf][3], ab + offA[kl][mf]);
            uint32_t bf[4][2];
#pragma unroll
            for (int np = 0; np < 2; ++np) {
                uint32_t r0, r1, r2, r3;
                ldsm4(r0, r1, r2, r3, bb + offB[kl][np]);
                bf[np * 2][0] = r0; bf[np * 2][1] = r1;
                bf[np * 2 + 1][0] = r2; bf[np * 2 + 1][1] = r3;
            }
#pragma unroll
            for (int mf = 0; mf < 4; ++mf)
#pragma unroll
                for (int nf = 0; nf < 4; ++nf) mma16816(acc[mf][nf], a[mf], bf[nf]);
        }
    }
    __syncthreads();  // compute done; reuse buf as reduction scratch

    float (*rowred)[4] = (float(*)[4])buf;
    float (*colred)[2] = (float(*)[2])(buf + 2048);

    // ---------- epilogue: e = __expf(20*acc), streaming store, partial sums ----------
    int qt = lane >> 2;
    int qc = lane & 3;
    float rsl[4][2];
    float csl[4][2];
#pragma unroll
    for (int i = 0; i < 4; i++) { rsl[i][0] = rsl[i][1] = 0.f; csl[i][0] = csl[i][1] = 0.f; }

    float* S = g_sim + (size_t)b * NN * NM;
#pragma unroll
    for (int mf = 0; mf < 4; ++mf) {
#pragma unroll
        for (int h = 0; h < 2; ++h) {
            int gr = n0 + warp_m * 64 + mf * 16 + qt + 8 * h;
            float* Sr = S + (size_t)gr * NM + m0 + warp_n * 32;
#pragma unroll
            for (int nf = 0; nf < 4; ++nf) {
                float e0 = __expf(20.0f * acc[mf][nf][h * 2 + 0]);
                float e1 = __expf(20.0f * acc[mf][nf][h * 2 + 1]);
                __stcs((float2*)(Sr + nf * 8 + qc * 2), make_float2(e0, e1));
                rsl[mf][h] += e0 + e1;
                csl[nf][0] += e0;
                csl[nf][1] += e1;
            }
        }
    }

#pragma unroll
    for (int mf = 0; mf < 4; ++mf)
#pragma unroll
        for (int h = 0; h < 2; ++h) {
            float v = rsl[mf][h];
            v += __shfl_xor_sync(0xffffffffu, v, 1);
            v += __shfl_xor_sync(0xffffffffu, v, 2);
            if (qc == 0) rowred[warp_m * 64 + mf * 16 + qt + 8 * h][warp_n] = v;
        }
#pragma unroll
    for (int nf = 0; nf < 4; ++nf)
#pragma unroll
        for (int c = 0; c < 2; ++c) {
            float v = csl[nf][c];
            v += __shfl_xor_sync(0xffffffffu, v, 4);
            v += __shfl_xor_sync(0xffffffffu, v, 8);
            v += __shfl_xor_sync(0xffffffffu, v, 16);
            if (qt == 0) colred[warp_n * 32 + nf * 8 + qc * 2 + c][warp_m] = v;
        }
    __syncthreads();

    if (tid < 128) {
        float rv = rowred[tid][0] + rowred[tid][1] + rowred[tid][2] + rowred[tid][3];
        g_rowsum_part[((size_t)b * NN + n0 + tid) * 32 + blockIdx.x] = rv;
        float cv = colred[tid][0] + colred[tid][1];
        g_colsum_part[((size_t)b * NM + m0 + tid) * 32 + blockIdx.y] = cv;
    }
}

// ---------------- final sum reduction -> reciprocals ----------------
__global__ void reduce_sums_kernel() {
    int warp = (blockIdx.x * blockDim.x + threadIdx.x) >> 5;  // 0..32767
    int lane = threadIdx.x & 31;
    if (warp < NB * NN) {
        float v = g_rowsum_part[warp * 32 + lane];
#pragma unroll
        for (int o = 16; o; o >>= 1) v += __shfl_xor_sync(0xffffffffu, v, o);
        if (lane == 0) g_rowinv[warp] = 1.0f / v;
    } else {
        int k = warp - NB * NN;
        float v = g_colsum_part[k * 32 + lane];
#pragma unroll
        for (int o = 16; o; o >>= 1) v += __shfl_xor_sync(0xffffffffu, v, o);
        if (lane == 0) g_colinv[k] = 1.0f / v;
    }
}

// ---------------- P pass: warp-per-4-rows, shared colmax ----------------
__global__ __launch_bounds__(256) void pmat_kernel() {
    __shared__ unsigned scm[NM];  // 16 KB column max of p
    int b = blockIdx.y;
    int tid = threadIdx.x, lane = tid & 31, w = tid >> 5;
    int row0 = blockIdx.x * 32 + w * 4;
    const float* S = g_sim + (size_t)b * NN * NM + (size_t)row0 * NM;
    const float* CI = g_colinv + b * NM;

    for (int i = tid; i < NM; i += 256) scm[i] = 0u;

    float ri[4];
#pragma unroll
    for (int r = 0; r < 4; ++r) ri[r] = __ldg(&g_rowinv[b * NN + row0 + r]);

    __syncthreads();

    float best[4] = {-1.f, -1.f, -1.f, -1.f};
    int bm[4] = {0, 0, 0, 0};

#pragma unroll 1
    for (int k = 0; k < 32; ++k) {
        int c = k * 128 + lane * 4;
        float4 civ = __ldg((const float4*)(CI + c));
        float cm[4] = {0.f, 0.f, 0.f, 0.f};
#pragma unroll
        for (int r = 0; r < 4; ++r) {
            float4 e = __ldcs((const float4*)(S + (size_t)r * NM + c));
            float q0 = (e.x * e.x) * civ.x;
            float q1 = (e.y * e.y) * civ.y;
            float q2 = (e.z * e.z) * civ.z;
            float q3 = (e.w * e.w) * civ.w;
            if (q0 > best[r]) { best[r] = q0; bm[r] = c; }
            if (q1 > best[r]) { best[r] = q1; bm[r] = c + 1; }
            if (q2 > best[r]) { best[r] = q2; bm[r] = c + 2; }
            if (q3 > best[r]) { best[r] = q3; bm[r] = c + 3; }
            cm[0] = fmaxf(cm[0], q0 * ri[r]);
            cm[1] = fmaxf(cm[1], q1 * ri[r]);
            cm[2] = fmaxf(cm[2], q2 * ri[r]);
            cm[3] = fmaxf(cm[3], q3 * ri[r]);
        }
        atomicMax(&scm[c + 0], __float_as_uint(cm[0]));
        atomicMax(&scm[c + 1], __float_as_uint(cm[1]));
        atomicMax(&scm[c + 2], __float_as_uint(cm[2]));
        atomicMax(&scm[c + 3], __float_as_uint(cm[3]));
    }

#pragma unroll
    for (int r = 0; r < 4; ++r) {
        float bq = best[r];
        int bj = bm[r];
#pragma unroll
        for (int o = 16; o; o >>= 1) {
            float ob = __shfl_xor_sync(0xffffffffu, bq, o);
            int obj = __shfl_xor_sync(0xffffffffu, bj, o);
            if (ob > bq || (ob == bq && obj < bj)) { bq = ob; bj = obj; }
        }
        if (lane == 0) {
            g_rowj[b * NN + row0 + r] = bj;
            g_rowP[b * NN + row0 + r] = bq * ri[r];
        }
    }

    __syncthreads();
    for (int i = tid; i < NM; i += 256)
        atomicMax(&g_colmaxP[b * NM + i], scm[i]);
}

// ---------------- finalize: 4 matches per 256-thread block, W in smem ----------------
__global__ __launch_bounds__(256) void finalize_kernel(const float* __restrict__ kA,
                                                       const float* __restrict__ descA,
                                                       const float* __restrict__ kB,
                                                       const float* __restrict__ descB,
                                                       const float* __restrict__ W,
                                                       const float* __restrict__ bl,
                                                       float* __restrict__ out) {
    __shared__ float sw[ND0 * NK];  // 32 KB
    __shared__ float sa[4][256], sb_[4][256];
    __shared__ float red[4][2][7];

    int g = threadIdx.x >> 6;
    int t = threadIdx.x & 63;
    int gid = blockIdx.x * 4 + g;
    int b = gid >> 12;

    for (int i = threadIdx.x * 4; i < ND0 * NK; i += 1024)
        *(float4*)(sw + i) = *(const float4*)(W + i);

    int j = g_rowj[gid];
    float Pij = g_rowP[gid];
    float cmj = __uint_as_float(g_colmaxP[b * NM + j]);
    bool valid = (Pij >= cmj) && (Pij > THRESH);

    const float* arow = descA + (size_t)gid * ND;
    const float* brow = descB + ((size_t)b * NM + j) * ND;
    *(float4*)(&sa[g][t * 4]) = *(const float4*)(arow + t * 4);
    *(float4*)(&sb_[g][t * 4]) = *(const float4*)(brow + t * 4);
    __syncthreads();

    float xA = 0.f, xB = 0.f;
#pragma unroll 8
    for (int d = 0; d < ND0; d++) {
        float wd = sw[d * NK + t];
        xA = fmaf(sa[g][d], wd, xA);
        xB = fmaf(sb_[g][d], wd, xB);
    }
    xA += __ldg(&bl[t]);
    xB += __ldg(&bl[t]);
    float spA = fmaxf(xA, 0.f) + log1pf(__expf(-fabsf(xA)));
    float spB = fmaxf(xB, 0.f) + log1pf(__expf(-fabsf(xB)));
    float wk = sqrtf(spA * spB);

    float x0 = sa[g][ND0 + 2 * t], x1 = sa[g][ND0 + 2 * t + 1];
    float y0 = sb_[g][ND0 + 2 * t], y1 = sb_[g][ND0 + 2 * t + 1];

    float vals[7];
    vals[0] = wk * x0 * x0;
    vals[1] = wk * x0 * x1;
    vals[2] = wk * x1 * x1;
    vals[3] = wk * y0 * x0;
    vals[4] = wk * y0 * x1;
    vals[5] = wk * y1 * x0;
    vals[6] = wk * y1 * x1;

#pragma unroll
    for (int i = 0; i < 7; i++) {
        float v = vals[i];
#pragma unroll
        for (int o = 16; o; o >>= 1) v += __shfl_xor_sync(0xffffffffu, v, o);
        if ((t & 31) == 0) red[g][t >> 5][i] = v;
    }
    __syncthreads();

    if (t == 0) {
        float g00 = red[g][0][0] + red[g][1][0] + EPS_G;
        float g01 = red[g][0][1] + red[g][1][1];
        float g11 = red[g][0][2] + red[g][1][2] + EPS_G;
        float c00 = red[g][0][3] + red[g][1][3];
        float c01 = red[g][0][4] + red[g][1][4];
        float c10 = red[g][0][5] + red[g][1][5];
        float c11 = red[g][0][6] + red[g][1][6];

        float dg = g00 * g11 - g01 * g01;
        float e00 = (c00 * g11 - c01 * g01) / dg;
        float e01 = (c01 * g00 - c00 * g01) / dg;
        float e10 = (c10 * g11 - c11 * g01) / dg;
        float e11 = (c11 * g00 - c10 * g01) / dg;

        float M00 = e00 * e00 + e10 * e10;
        float M01 = e00 * e01 + e10 * e11;
        float M11 = e01 * e01 + e11 * e11;
        float tr = M00 + M11;
        float dd = M00 * M11 - M01 * M01;
        float disc = sqrtf(fmaxf(0.25f * tr * tr - dd, 0.f));
        float shi = sqrtf(0.5f * tr + disc);
        float slo = sqrtf(fmaxf(0.5f * tr - disc, 0.f));

        bool good = isfinite(shi + slo) && (shi < 3.0f) && (slo > (1.0f / 3.0f));
        float dete = e00 * e11 - e01 * e10;
        good = good && (dete > 0.f);
        bool vfinal = valid && good;

        const int BN = NB * NN;
        out[(size_t)gid * 2 + 0] = kA[(size_t)gid * 2 + 0];
        out[(size_t)gid * 2 + 1] = kA[(size_t)gid * 2 + 1];
        out[(size_t)BN * 2 + (size_t)gid * 2 + 0] = kB[((size_t)b * NM + j) * 2 + 0];
        out[(size_t)BN * 2 + (size_t)gid * 2 + 1] = kB[((size_t)b * NM + j) * 2 + 1];
        out[(size_t)BN * 4 + gid] = (float)j;
        out[(size_t)BN * 5 + gid] = vfinal ? 1.0f : 0.0f;
    }
}

// ---------------- launch (single stream, R10 schedule) ----------------
extern "C" void kernel_launch(void* const* d_in, const int* in_sizes, int n_in,
                              void* d_out, int out_size) {
    const float* kA = (const float*)d_in[0];
    const float* dA = (const float*)d_in[1];
    const float* kB = (const float*)d_in[2];
    const float* dB = (const float*)d_in[3];
    const float* W = (const float*)d_in[4];
    const float* bl = (const float*)d_in[5];
    float* out = (float*)d_out;

    static int attr_set = 0;
    if (!attr_set) {
        cudaFuncSetAttribute(gemm16_kernel,
                             cudaFuncAttributeMaxDynamicSharedMemorySize, GSMEM);
        attr_set = 1;
    }

    normalize_split_kernel<<<2 * NB * NN / 4, 256>>>(dA, dB);

    dim3 g(NM / 128, NN / 128, NB);
    gemm16_kernel<<<g, 256, GSMEM>>>();
    reduce_sums_kernel<<<(2 * NB * NN * 32 + 255) / 256, 256>>>();
    pmat_kernel<<<dim3(NN / 32, NB), 256>>>();
    finalize_kernel<<<NB * NN / 4, 256>>>(kA, dA, kB, dB, W, bl, out);
}